// round 1
// baseline (speedup 1.0000x reference)
#include <cuda_runtime.h>
#include <math.h>
#include <stdint.h>

#define L_LEVELS 16
#define TBL (1 << 19)
#define TMASK (TBL - 1)
#define BLOCK 128

struct Scales { float s[L_LEVELS]; };

__device__ __forceinline__ float relu(float x) { return fmaxf(x, 0.0f); }

// Dense level: idx = min(sum corner*stride, T-1)
template <int R>
__device__ __forceinline__ void enc_level_dense(const float in4[4], float scale,
                                                const float2* __restrict__ gt,
                                                float& o0, float& o1) {
    float fr[4], omf[4];
    int k0[4], k1[4];
    const int S[4] = {1, R, R * R, R * R * R};
#pragma unroll
    for (int d = 0; d < 4; d++) {
        float p = in4[d] * scale + 0.5f;
        float g = floorf(p);
        fr[d] = p - g;
        omf[d] = 1.0f - fr[d];
        int gi = (int)g;
        k0[d] = gi * S[d];
        k1[d] = k0[d] + S[d];
    }
    float f0 = 0.0f, f1 = 0.0f;
#pragma unroll
    for (int c = 0; c < 16; c++) {
        int idx = ((c & 1) ? k1[0] : k0[0]) + ((c & 2) ? k1[1] : k0[1]) +
                  ((c & 4) ? k1[2] : k0[2]) + ((c & 8) ? k1[3] : k0[3]);
        idx = min(idx, TMASK);
        float w = ((c & 1) ? fr[0] : omf[0]) * ((c & 2) ? fr[1] : omf[1]) *
                  ((c & 4) ? fr[2] : omf[2]) * ((c & 8) ? fr[3] : omf[3]);
        float2 v = __ldg(&gt[idx]);
        f0 = fmaf(w, v.x, f0);
        f1 = fmaf(w, v.y, f1);
    }
    o0 = f0;
    o1 = f1;
}

// Hash level: idx = (c0*P0 ^ c1*P1 ^ c2*P2 ^ c3*P3) & (T-1)
__device__ __forceinline__ void enc_level_hash(const float in4[4], float scale,
                                               const float2* __restrict__ gt,
                                               float& o0, float& o1) {
    const uint32_t P[4] = {1u, 2654435761u, 805459861u, 3674351687u};
    float fr[4], omf[4];
    uint32_t k0[4], k1[4];
#pragma unroll
    for (int d = 0; d < 4; d++) {
        float p = in4[d] * scale + 0.5f;
        float g = floorf(p);
        fr[d] = p - g;
        omf[d] = 1.0f - fr[d];
        uint32_t gi = (uint32_t)(int)g;
        k0[d] = gi * P[d];
        k1[d] = k0[d] + P[d];
    }
    float f0 = 0.0f, f1 = 0.0f;
#pragma unroll
    for (int c = 0; c < 16; c++) {
        uint32_t h = (((c & 1) ? k1[0] : k0[0]) ^ ((c & 2) ? k1[1] : k0[1]) ^
                      ((c & 4) ? k1[2] : k0[2]) ^ ((c & 8) ? k1[3] : k0[3]));
        uint32_t idx = h & TMASK;
        float w = ((c & 1) ? fr[0] : omf[0]) * ((c & 2) ? fr[1] : omf[1]) *
                  ((c & 4) ? fr[2] : omf[2]) * ((c & 8) ? fr[3] : omf[3]);
        float2 v = __ldg(&gt[idx]);
        f0 = fmaf(w, v.x, f0);
        f1 = fmaf(w, v.y, f1);
    }
    o0 = f0;
    o1 = f1;
}

__global__ void __launch_bounds__(BLOCK)
htrf_kernel(const float4* __restrict__ xyzs,   // [N,4]
            const float* __restrict__ dirs,    // [N,3]
            const float2* __restrict__ grid,   // [L,T] of float2
            const float* __restrict__ gW1,     // [64,32]
            const float* __restrict__ gW2,     // [16,64]
            const float* __restrict__ gWc1,    // [64,32]
            const float* __restrict__ gWc2,    // [64,64]
            const float* __restrict__ gWc3,    // [3,64]
            float* __restrict__ out,           // [N*3 color | N sigma]
            int N, Scales sc) {
    __shared__ float sW1[64 * 32];
    __shared__ float sW2[16 * 64];
    __shared__ float sWc1[64 * 32];
    __shared__ float sWc2[64 * 64];
    __shared__ float sWc3[3 * 64];

    for (int i = threadIdx.x; i < 64 * 32; i += BLOCK) sW1[i] = gW1[i];
    for (int i = threadIdx.x; i < 16 * 64; i += BLOCK) sW2[i] = gW2[i];
    for (int i = threadIdx.x; i < 64 * 32; i += BLOCK) sWc1[i] = gWc1[i];
    for (int i = threadIdx.x; i < 64 * 64; i += BLOCK) sWc2[i] = gWc2[i];
    for (int i = threadIdx.x; i < 3 * 64; i += BLOCK) sWc3[i] = gWc3[i];
    __syncthreads();

    int t = blockIdx.x * BLOCK + threadIdx.x;
    if (t >= N) return;

    float4 xin = __ldg(&xyzs[t]);
    float in4[4];
    in4[0] = (xin.x + 1.0f) * 0.5f;
    in4[1] = (xin.y + 1.0f) * 0.5f;
    in4[2] = (xin.z + 1.0f) * 0.5f;
    in4[3] = xin.w;

    // ---- hash encode: hr[32] ----
    float hr[32];
    enc_level_dense<8>(in4, sc.s[0], grid + 0 * TBL, hr[0], hr[1]);
    enc_level_dense<12>(in4, sc.s[1], grid + 1 * TBL, hr[2], hr[3]);
    enc_level_dense<17>(in4, sc.s[2], grid + 2 * TBL, hr[4], hr[5]);
    enc_level_dense<25>(in4, sc.s[3], grid + 3 * TBL, hr[6], hr[7]);
#pragma unroll
    for (int l = 4; l < L_LEVELS; l++) {
        enc_level_hash(in4, sc.s[l], grid + l * TBL, hr[2 * l], hr[2 * l + 1]);
    }

    // ---- density MLP: h16 = relu(hr @ W1^T) @ W2^T (fused) ----
    float h16[16];
#pragma unroll
    for (int j = 0; j < 16; j++) h16[j] = 0.0f;
    for (int k = 0; k < 64; k++) {
        float v = 0.0f;
        const float* w1row = &sW1[k * 32];
#pragma unroll
        for (int i = 0; i < 32; i++) v = fmaf(hr[i], w1row[i], v);
        v = relu(v);
#pragma unroll
        for (int j = 0; j < 16; j++) h16[j] = fmaf(v, sW2[j * 64 + k], h16[j]);
    }
    float sigma = expf(h16[0]);

    // ---- spherical harmonics deg 4 ----
    float dx = dirs[3 * t + 0] * 2.0f - 1.0f;
    float dy = dirs[3 * t + 1] * 2.0f - 1.0f;
    float dz = dirs[3 * t + 2] * 2.0f - 1.0f;
    float xy = dx * dy, xz = dx * dz, yz = dy * dz;
    float x2 = dx * dx, y2 = dy * dy, z2 = dz * dz;
    float sh[16];
    sh[0] = 0.28209479177387814f;
    sh[1] = -0.48860251190291987f * dy;
    sh[2] = 0.48860251190291987f * dz;
    sh[3] = -0.48860251190291987f * dx;
    sh[4] = 1.0925484305920792f * xy;
    sh[5] = -1.0925484305920792f * yz;
    sh[6] = 0.94617469575756f * z2 - 0.31539156525252f;
    sh[7] = -1.0925484305920792f * xz;
    sh[8] = 0.5462742152960396f * x2 - 0.5462742152960396f * y2;
    sh[9] = 0.5900435899266435f * dy * (-3.0f * x2 + y2);
    sh[10] = 2.890611442640554f * xy * dz;
    sh[11] = 0.4570457994644657f * dy * (1.0f - 5.0f * z2);
    sh[12] = 0.3731763325901154f * dz * (5.0f * z2 - 3.0f);
    sh[13] = 0.4570457994644657f * dx * (1.0f - 5.0f * z2);
    sh[14] = 1.445305721320277f * dz * (x2 - y2);
    sh[15] = 0.5900435899266435f * dx * (-x2 + 3.0f * y2);

    // ---- color MLP: ci=[sh,h16]; a2 = relu(ci@Wc1^T)@Wc2^T (fused) ----
    float a2[64];
#pragma unroll
    for (int j = 0; j < 64; j++) a2[j] = 0.0f;
    for (int k = 0; k < 64; k++) {
        float v = 0.0f;
        const float* wrow = &sWc1[k * 32];
#pragma unroll
        for (int i = 0; i < 16; i++) v = fmaf(sh[i], wrow[i], v);
#pragma unroll
        for (int i = 0; i < 16; i++) v = fmaf(h16[i], wrow[16 + i], v);
        v = relu(v);
#pragma unroll
        for (int j = 0; j < 64; j++) a2[j] = fmaf(v, sWc2[j * 64 + k], a2[j]);
    }
    float c0 = 0.0f, c1 = 0.0f, c2 = 0.0f;
#pragma unroll
    for (int k = 0; k < 64; k++) {
        float v = relu(a2[k]);
        c0 = fmaf(v, sWc3[0 * 64 + k], c0);
        c1 = fmaf(v, sWc3[1 * 64 + k], c1);
        c2 = fmaf(v, sWc3[2 * 64 + k], c2);
    }
    c0 = 1.0f / (1.0f + expf(-c0));
    c1 = 1.0f / (1.0f + expf(-c1));
    c2 = 1.0f / (1.0f + expf(-c2));

    out[t * 3 + 0] = c0;
    out[t * 3 + 1] = c1;
    out[t * 3 + 2] = c2;
    out[3 * N + t] = sigma;
}

extern "C" void kernel_launch(void* const* d_in, const int* in_sizes, int n_in,
                              void* d_out, int out_size) {
    const float4* xyzs = (const float4*)d_in[0];
    const float* dirs = (const float*)d_in[1];
    const float2* grid = (const float2*)d_in[2];
    const float* W1 = (const float*)d_in[3];
    const float* W2 = (const float*)d_in[4];
    const float* Wc1 = (const float*)d_in[5];
    const float* Wc2 = (const float*)d_in[6];
    const float* Wc3 = (const float*)d_in[7];
    float* out = (float*)d_out;

    int N = in_sizes[0] / 4;

    Scales sc;
    const double log2B = log(2048.0 / 8.0) / 15.0 / log(2.0);  // = 8/15
    for (int l = 0; l < L_LEVELS; l++) {
        double scale = exp2((double)l * log2B) * 8.0 - 1.0;
        sc.s[l] = (float)scale;
    }

    int blocks = (N + BLOCK - 1) / BLOCK;
    htrf_kernel<<<blocks, BLOCK>>>(xyzs, dirs, grid, W1, W2, Wc1, Wc2, Wc3,
                                   out, N, sc);
}

// round 2
// speedup vs baseline: 1.1152x; 1.1152x over previous
#include <cuda_runtime.h>
#include <math.h>
#include <stdint.h>

#define L_LEVELS 16
#define TBL (1 << 19)
#define TMASK (TBL - 1)
#define BLOCK 128

struct Scales { float s[L_LEVELS]; };

__device__ __forceinline__ float relu(float x) { return fmaxf(x, 0.0f); }

// Dense level: idx = min(sum corner*stride, T-1)
template <int R>
__device__ __forceinline__ void enc_level_dense(const float in4[4], float scale,
                                                const float2* __restrict__ gt,
                                                float& o0, float& o1) {
    float fr[4], omf[4];
    int k0[4], k1[4];
    const int S[4] = {1, R, R * R, R * R * R};
#pragma unroll
    for (int d = 0; d < 4; d++) {
        float p = in4[d] * scale + 0.5f;
        float g = floorf(p);
        fr[d] = p - g;
        omf[d] = 1.0f - fr[d];
        int gi = (int)g;
        k0[d] = gi * S[d];
        k1[d] = k0[d] + S[d];
    }
    float f0 = 0.0f, f1 = 0.0f;
#pragma unroll
    for (int c = 0; c < 16; c++) {
        int idx = ((c & 1) ? k1[0] : k0[0]) + ((c & 2) ? k1[1] : k0[1]) +
                  ((c & 4) ? k1[2] : k0[2]) + ((c & 8) ? k1[3] : k0[3]);
        idx = min(idx, TMASK);
        float w = ((c & 1) ? fr[0] : omf[0]) * ((c & 2) ? fr[1] : omf[1]) *
                  ((c & 4) ? fr[2] : omf[2]) * ((c & 8) ? fr[3] : omf[3]);
        float2 v = __ldg(&gt[idx]);
        f0 = fmaf(w, v.x, f0);
        f1 = fmaf(w, v.y, f1);
    }
    o0 = f0;
    o1 = f1;
}

// Hash level: idx = (c0*P0 ^ c1*P1 ^ c2*P2 ^ c3*P3) & (T-1)
__device__ __forceinline__ void enc_level_hash(const float in4[4], float scale,
                                               const float2* __restrict__ gt,
                                               float& o0, float& o1) {
    const uint32_t P[4] = {1u, 2654435761u, 805459861u, 3674351687u};
    float fr[4], omf[4];
    uint32_t k0[4], k1[4];
#pragma unroll
    for (int d = 0; d < 4; d++) {
        float p = in4[d] * scale + 0.5f;
        float g = floorf(p);
        fr[d] = p - g;
        omf[d] = 1.0f - fr[d];
        uint32_t gi = (uint32_t)(int)g;
        k0[d] = gi * P[d];
        k1[d] = k0[d] + P[d];
    }
    float f0 = 0.0f, f1 = 0.0f;
#pragma unroll
    for (int c = 0; c < 16; c++) {
        uint32_t h = (((c & 1) ? k1[0] : k0[0]) ^ ((c & 2) ? k1[1] : k0[1]) ^
                      ((c & 4) ? k1[2] : k0[2]) ^ ((c & 8) ? k1[3] : k0[3]));
        uint32_t idx = h & TMASK;
        float w = ((c & 1) ? fr[0] : omf[0]) * ((c & 2) ? fr[1] : omf[1]) *
                  ((c & 4) ? fr[2] : omf[2]) * ((c & 8) ? fr[3] : omf[3]);
        float2 v = __ldg(&gt[idx]);
        f0 = fmaf(w, v.x, f0);
        f1 = fmaf(w, v.y, f1);
    }
    o0 = f0;
    o1 = f1;
}

__global__ void __launch_bounds__(BLOCK)
htrf_kernel(const float4* __restrict__ xyzs,   // [N,4]
            const float* __restrict__ dirs,    // [N,3]
            const float2* __restrict__ grid,   // [L,T] of float2
            const float4* __restrict__ gW1,    // [64,32] -> 512 float4
            const float* __restrict__ gW2,     // [16,64]
            const float4* __restrict__ gWc1,   // [64,32] -> 512 float4
            const float* __restrict__ gWc2,    // [64,64]
            const float* __restrict__ gWc3,    // [3,64]
            float* __restrict__ out,           // [N*3 color | N sigma]
            int N, Scales sc) {
    // All weights stored so inner loops read contiguous float4 broadcasts.
    __shared__ float4 sW1[64 * 8];    // row-major rows of W1
    __shared__ float4 sW2T[64 * 4];   // sW2T[k*4+q] = W2[4q..4q+3][k]
    __shared__ float4 sWc1[64 * 8];
    __shared__ float4 sWc2T[64 * 16]; // sWc2T[k*16+q] = Wc2[4q..4q+3][k]
    __shared__ float4 sWc3T[64];      // {Wc3[0][k], Wc3[1][k], Wc3[2][k], 0}

    for (int i = threadIdx.x; i < 512; i += BLOCK) sW1[i] = gW1[i];
    for (int i = threadIdx.x; i < 512; i += BLOCK) sWc1[i] = gWc1[i];
    for (int i = threadIdx.x; i < 16 * 64; i += BLOCK) {
        int j = i >> 6, k = i & 63;
        ((float*)sW2T)[k * 16 + j] = gW2[i];
    }
    for (int i = threadIdx.x; i < 64 * 64; i += BLOCK) {
        int j = i >> 6, k = i & 63;
        ((float*)sWc2T)[k * 64 + j] = gWc2[i];
    }
    for (int i = threadIdx.x; i < 256; i += BLOCK) {
        int k = i >> 2, j = i & 3;
        ((float*)sWc3T)[i] = (j < 3) ? gWc3[j * 64 + k] : 0.0f;
    }
    __syncthreads();

    int t = blockIdx.x * BLOCK + threadIdx.x;
    if (t >= N) return;

    float4 xin = __ldg(&xyzs[t]);
    float in4[4];
    in4[0] = (xin.x + 1.0f) * 0.5f;
    in4[1] = (xin.y + 1.0f) * 0.5f;
    in4[2] = (xin.z + 1.0f) * 0.5f;
    in4[3] = xin.w;

    // ---- hash encode: hr[32] ----
    float hr[32];
    enc_level_dense<8>(in4, sc.s[0], grid + 0 * TBL, hr[0], hr[1]);
    enc_level_dense<12>(in4, sc.s[1], grid + 1 * TBL, hr[2], hr[3]);
    enc_level_dense<17>(in4, sc.s[2], grid + 2 * TBL, hr[4], hr[5]);
    enc_level_dense<25>(in4, sc.s[3], grid + 3 * TBL, hr[6], hr[7]);
#pragma unroll
    for (int l = 4; l < L_LEVELS; l++) {
        enc_level_hash(in4, sc.s[l], grid + l * TBL, hr[2 * l], hr[2 * l + 1]);
    }

    // ---- density MLP: h16 = relu(hr @ W1^T) @ W2^T (fused) ----
    float h16[16];
#pragma unroll
    for (int j = 0; j < 16; j++) h16[j] = 0.0f;
    for (int k = 0; k < 64; k++) {
        float v = 0.0f;
        const float4* w1row = &sW1[k * 8];
#pragma unroll
        for (int q = 0; q < 8; q++) {
            float4 w = w1row[q];
            v = fmaf(hr[4 * q + 0], w.x, v);
            v = fmaf(hr[4 * q + 1], w.y, v);
            v = fmaf(hr[4 * q + 2], w.z, v);
            v = fmaf(hr[4 * q + 3], w.w, v);
        }
        v = relu(v);
        const float4* w2col = &sW2T[k * 4];
#pragma unroll
        for (int q = 0; q < 4; q++) {
            float4 w = w2col[q];
            h16[4 * q + 0] = fmaf(v, w.x, h16[4 * q + 0]);
            h16[4 * q + 1] = fmaf(v, w.y, h16[4 * q + 1]);
            h16[4 * q + 2] = fmaf(v, w.z, h16[4 * q + 2]);
            h16[4 * q + 3] = fmaf(v, w.w, h16[4 * q + 3]);
        }
    }
    float sigma = __expf(h16[0]);

    // ---- spherical harmonics deg 4 ----
    float dx = dirs[3 * t + 0] * 2.0f - 1.0f;
    float dy = dirs[3 * t + 1] * 2.0f - 1.0f;
    float dz = dirs[3 * t + 2] * 2.0f - 1.0f;
    float xy = dx * dy, xz = dx * dz, yz = dy * dz;
    float x2 = dx * dx, y2 = dy * dy, z2 = dz * dz;
    float sh[16];
    sh[0] = 0.28209479177387814f;
    sh[1] = -0.48860251190291987f * dy;
    sh[2] = 0.48860251190291987f * dz;
    sh[3] = -0.48860251190291987f * dx;
    sh[4] = 1.0925484305920792f * xy;
    sh[5] = -1.0925484305920792f * yz;
    sh[6] = 0.94617469575756f * z2 - 0.31539156525252f;
    sh[7] = -1.0925484305920792f * xz;
    sh[8] = 0.5462742152960396f * x2 - 0.5462742152960396f * y2;
    sh[9] = 0.5900435899266435f * dy * (-3.0f * x2 + y2);
    sh[10] = 2.890611442640554f * xy * dz;
    sh[11] = 0.4570457994644657f * dy * (1.0f - 5.0f * z2);
    sh[12] = 0.3731763325901154f * dz * (5.0f * z2 - 3.0f);
    sh[13] = 0.4570457994644657f * dx * (1.0f - 5.0f * z2);
    sh[14] = 1.445305721320277f * dz * (x2 - y2);
    sh[15] = 0.5900435899266435f * dx * (-x2 + 3.0f * y2);

    // ---- color MLP: ci=[sh,h16]; a2 = relu(ci@Wc1^T)@Wc2^T (fused) ----
    float a2[64];
#pragma unroll
    for (int j = 0; j < 64; j++) a2[j] = 0.0f;
    for (int k = 0; k < 64; k++) {
        float v = 0.0f;
        const float4* wrow = &sWc1[k * 8];
#pragma unroll
        for (int q = 0; q < 4; q++) {
            float4 w = wrow[q];
            v = fmaf(sh[4 * q + 0], w.x, v);
            v = fmaf(sh[4 * q + 1], w.y, v);
            v = fmaf(sh[4 * q + 2], w.z, v);
            v = fmaf(sh[4 * q + 3], w.w, v);
        }
#pragma unroll
        for (int q = 0; q < 4; q++) {
            float4 w = wrow[4 + q];
            v = fmaf(h16[4 * q + 0], w.x, v);
            v = fmaf(h16[4 * q + 1], w.y, v);
            v = fmaf(h16[4 * q + 2], w.z, v);
            v = fmaf(h16[4 * q + 3], w.w, v);
        }
        v = relu(v);
        const float4* wc2col = &sWc2T[k * 16];
#pragma unroll
        for (int q = 0; q < 16; q++) {
            float4 w = wc2col[q];
            a2[4 * q + 0] = fmaf(v, w.x, a2[4 * q + 0]);
            a2[4 * q + 1] = fmaf(v, w.y, a2[4 * q + 1]);
            a2[4 * q + 2] = fmaf(v, w.z, a2[4 * q + 2]);
            a2[4 * q + 3] = fmaf(v, w.w, a2[4 * q + 3]);
        }
    }
    float c0 = 0.0f, c1 = 0.0f, c2 = 0.0f;
#pragma unroll
    for (int k = 0; k < 64; k++) {
        float v = relu(a2[k]);
        float4 w = sWc3T[k];
        c0 = fmaf(v, w.x, c0);
        c1 = fmaf(v, w.y, c1);
        c2 = fmaf(v, w.z, c2);
    }
    c0 = 1.0f / (1.0f + __expf(-c0));
    c1 = 1.0f / (1.0f + __expf(-c1));
    c2 = 1.0f / (1.0f + __expf(-c2));

    out[t * 3 + 0] = c0;
    out[t * 3 + 1] = c1;
    out[t * 3 + 2] = c2;
    out[3 * N + t] = sigma;
}

extern "C" void kernel_launch(void* const* d_in, const int* in_sizes, int n_in,
                              void* d_out, int out_size) {
    const float4* xyzs = (const float4*)d_in[0];
    const float* dirs = (const float*)d_in[1];
    const float2* grid = (const float2*)d_in[2];
    const float4* W1 = (const float4*)d_in[3];
    const float* W2 = (const float*)d_in[4];
    const float4* Wc1 = (const float4*)d_in[5];
    const float* Wc2 = (const float*)d_in[6];
    const float* Wc3 = (const float*)d_in[7];
    float* out = (float*)d_out;

    int N = in_sizes[0] / 4;

    Scales sc;
    const double log2B = log(2048.0 / 8.0) / 15.0 / log(2.0);  // = 8/15
    for (int l = 0; l < L_LEVELS; l++) {
        double scale = exp2((double)l * log2B) * 8.0 - 1.0;
        sc.s[l] = (float)scale;
    }

    int blocks = (N + BLOCK - 1) / BLOCK;
    htrf_kernel<<<blocks, BLOCK>>>(xyzs, dirs, grid, W1, W2, Wc1, Wc2, Wc3,
                                   out, N, sc);
}